// round 16
// baseline (speedup 1.0000x reference)
#include <cuda_runtime.h>

#define BATCH 32
#define CIN   64
#define COUT  64
#define HW    64
#define PLANE 4096
#define KK    9
#define SSTR  132   // words per channel row of S (128 px + 4 pad)

#define FMA2(a, s, w) asm("fma.rn.f32x2 %0, %1, %2, %0;" : "+l"(a) : "l"(s), "l"(w))
#define DUP2(d, f)    asm("mov.b64 %0, {%1, %1};" : "=l"(d) : "f"(f))

// Scratch
__device__ float g_d[BATCH * COUT * PLANE];   // pre-norm conv output (~33.5 MB)
__device__ float g_wt[KK * CIN * COUT];       // transposed weights [k][c][o]

__global__ void transpose_w(const float* __restrict__ w) {
    int idx = blockIdx.x * 256 + threadIdx.x;
    if (idx < COUT * CIN * KK) {
        int o = idx / (CIN * KK);
        int r = idx % (CIN * KK);
        int c = r / KK;
        int k = r % KK;
        g_wt[(k * CIN + c) * COUT + o] = w[idx];
    }
}

__global__ void dummy_kernel() {}

// Block: 128 pixels x 64 outputs. 256 threads.
// Phase A: 2 threads per pixel, 32 channels each, blended into S[c][px].
// Phase B: thread = 4 pixels x 8 outputs register tile. 24 warps/SM.
__global__ __launch_bounds__(256, 3)
void deform_kernel(const float* __restrict__ x,
                   const float* __restrict__ offset)
{
    __shared__ float S[CIN * SSTR];   // 33792 B

    const int t   = threadIdx.x;
    const int seg = blockIdx.x & 31;
    const int b   = blockIdx.x >> 5;

    // Phase A role: 2 threads per pixel, 32 channels each
    const int pixA  = t & 127;
    const int chalf = t >> 7;
    const int gpixA = seg * 128 + pixA;
    const int rowA  = gpixA >> 6;
    const int colA  = gpixA & 63;
    float* sdstA = S + (chalf * 32) * SSTR + pixA;

    // Phase B role: og = 8-output group (t>>5), pg = 4-pixel group (t&31)
    const int og = t >> 5;            // 0..7
    const int pg = t & 31;            // 0..31
    const int o0 = og * 8;
    const float* sbase = S + pg * 4;  // 16B-aligned chunk per lane

    const float* xb   = x + (size_t)b * CIN * PLANE;
    const float* offb = offset + (size_t)b * (2 * KK) * PLANE;

    // acc[pixel-pair][o] : 4 pixels x 8 outs = 16 packed f32x2 (32 regs)
    unsigned long long acc[2][8];
    #pragma unroll
    for (int i = 0; i < 2; i++)
        #pragma unroll
        for (int j = 0; j < 8; j++) acc[i][j] = 0ull;

    #pragma unroll 1
    for (int k = 0; k < KK; k++) {
        if (k > 0) __syncthreads();   // previous Phase B done reading S

        // ---------------- Phase A: sample into S ----------------
        {
            const int ky = k / 3;
            const int kx = k - 3 * ky;
            const float oy = __ldg(offb + (2 * k)     * PLANE + gpixA);
            const float ox = __ldg(offb + (2 * k + 1) * PLANE + gpixA);
            const float py = (float)(rowA - 1 + ky) + oy;
            const float px = (float)(colA - 1 + kx) + ox;
            const float y0f = floorf(py), x0f = floorf(px);
            const float fy = py - y0f,  fx = px - x0f;
            const int y0 = (int)y0f, x0 = (int)x0f;
            const int y1 = y0 + 1,   x1 = x0 + 1;
            const float vy0 = (y0 >= 0 && y0 < HW) ? 1.f : 0.f;
            const float vy1 = (y1 >= 0 && y1 < HW) ? 1.f : 0.f;
            const float vx0 = (x0 >= 0 && x0 < HW) ? 1.f : 0.f;
            const float vx1 = (x1 >= 0 && x1 < HW) ? 1.f : 0.f;
            const int cy0 = min(max(y0, 0), HW - 1), cy1 = min(max(y1, 0), HW - 1);
            const int cx0 = min(max(x0, 0), HW - 1), cx1 = min(max(x1, 0), HW - 1);
            const float W00 = (1.f - fy) * (1.f - fx) * vy0 * vx0;
            const float W01 = (1.f - fy) * fx        * vy0 * vx1;
            const float W10 = fy        * (1.f - fx) * vy1 * vx0;
            const float W11 = fy        * fx         * vy1 * vx1;

            const float* p00 = xb + (size_t)(chalf * 32) * PLANE + cy0 * HW + cx0;
            const float* p01 = xb + (size_t)(chalf * 32) * PLANE + cy0 * HW + cx1;
            const float* p10 = xb + (size_t)(chalf * 32) * PLANE + cy1 * HW + cx0;
            const float* p11 = xb + (size_t)(chalf * 32) * PLANE + cy1 * HW + cx1;

            #pragma unroll 8
            for (int cc = 0; cc < 32; cc++) {
                const float a00 = __ldg(p00 + cc * PLANE);
                const float a01 = __ldg(p01 + cc * PLANE);
                const float a10 = __ldg(p10 + cc * PLANE);
                const float a11 = __ldg(p11 + cc * PLANE);
                float s = W00 * a00;
                s = fmaf(W01, a01, s);
                s = fmaf(W10, a10, s);
                s = fmaf(W11, a11, s);
                sdstA[cc * SSTR] = s;
            }
        }
        __syncthreads();

        // ---------------- Phase B: GEMM from S x Wt ----------------
        {
            const float* wbase = g_wt + (size_t)k * CIN * COUT + o0;

            #pragma unroll 4
            for (int c = 0; c < CIN; c++) {
                const float4 w0 = __ldg((const float4*)(wbase + (size_t)c * COUT));
                const float4 w1 = __ldg((const float4*)(wbase + (size_t)c * COUT + 4));

                const ulonglong2 sA = *(const ulonglong2*)(sbase + c * SSTR);

                unsigned long long W2[8];
                DUP2(W2[0], w0.x); DUP2(W2[1], w0.y);
                DUP2(W2[2], w0.z); DUP2(W2[3], w0.w);
                DUP2(W2[4], w1.x); DUP2(W2[5], w1.y);
                DUP2(W2[6], w1.z); DUP2(W2[7], w1.w);

                #pragma unroll
                for (int oo = 0; oo < 8; oo++) {
                    FMA2(acc[0][oo], sA.x, W2[oo]);
                    FMA2(acc[1][oo], sA.y, W2[oo]);
                }
            }
        }
    }

    // Epilogue: write d (lane pg covers 4 consecutive pixels -> 512B coalesced per warp).
    float* dbase = g_d + ((size_t)b * COUT + o0) * PLANE + seg * 128 + pg * 4;
    #pragma unroll
    for (int oo = 0; oo < 8; oo++) {
        float4 v;
        v.x = __uint_as_float((unsigned)(acc[0][oo] & 0xffffffffull));
        v.y = __uint_as_float((unsigned)(acc[0][oo] >> 32));
        v.z = __uint_as_float((unsigned)(acc[1][oo] & 0xffffffffull));
        v.w = __uint_as_float((unsigned)(acc[1][oo] >> 32));
        *(float4*)(dbase + (size_t)oo * PLANE) = v;
    }
}

// One block per (b, o) plane: single-read stats + normalize + tanh.
__global__ __launch_bounds__(256)
void norm_kernel(const float* __restrict__ gamma_p,
                 const float* __restrict__ beta_p,
                 float* __restrict__ out)
{
    __shared__ float red[16];
    __shared__ float bcast[2];

    const int bo = blockIdx.x;
    const int t  = threadIdx.x;
    const float4* src = reinterpret_cast<const float4*>(g_d + (size_t)bo * PLANE);

    float4 v[4];
    float s = 0.f, q = 0.f;
    #pragma unroll
    for (int i = 0; i < 4; i++) {
        v[i] = src[t + 256 * i];
        s += v[i].x + v[i].y + v[i].z + v[i].w;
        q += v[i].x * v[i].x + v[i].y * v[i].y + v[i].z * v[i].z + v[i].w * v[i].w;
    }
    #pragma unroll
    for (int d = 16; d > 0; d >>= 1) {
        s += __shfl_xor_sync(0xffffffffu, s, d);
        q += __shfl_xor_sync(0xffffffffu, q, d);
    }
    const int w = t >> 5, lane = t & 31;
    if (lane == 0) { red[w] = s; red[8 + w] = q; }
    __syncthreads();
    if (t == 0) {
        float S = 0.f, Q = 0.f;
        #pragma unroll
        for (int i = 0; i < 8; i++) { S += red[i]; Q += red[8 + i]; }
        const float n  = (float)PLANE;
        const float mu = S / n;
        float var = (Q - S * S / n) / (n - 1.f);
        var = fmaxf(var, 0.f);
        const float sd = sqrtf(var);
        bcast[0] = mu;
        bcast[1] = __ldg(gamma_p) / (sd + 1e-8f);
    }
    __syncthreads();
    const float mu    = bcast[0];
    const float scale = bcast[1];
    const float beta  = __ldg(beta_p);

    float4* o = reinterpret_cast<float4*>(out + (size_t)bo * PLANE);
    #pragma unroll
    for (int i = 0; i < 4; i++) {
        float4 r;
        r.x = tanhf((v[i].x - mu) * scale + beta);
        r.y = tanhf((v[i].y - mu) * scale + beta);
        r.z = tanhf((v[i].z - mu) * scale + beta);
        r.w = tanhf((v[i].w - mu) * scale + beta);
        o[t + 256 * i] = r;
    }
}

extern "C" void kernel_launch(void* const* d_in, const int* in_sizes, int n_in,
                              void* d_out, int out_size)
{
    const float* x      = (const float*)d_in[0];
    const float* offset = (const float*)d_in[1];
    const float* weight = (const float*)d_in[2];
    const float* gamma  = (const float*)d_in[3];
    const float* beta   = (const float*)d_in[4];

    // Launch order chosen so ncu (-s 5, with 2 harness pre-launches) profiles
    // position (5-2) mod 5 = 3 = deform_kernel.
    transpose_w<<<144, 256>>>(weight);       // pos 0
    dummy_kernel<<<1, 32>>>();               // pos 1
    dummy_kernel<<<1, 32>>>();               // pos 2
    deform_kernel<<<BATCH * 32, 256>>>(x, offset);   // pos 3  (1024 blocks)
    norm_kernel<<<BATCH * COUT, 256>>>(gamma, beta, (float*)d_out);  // pos 4
}

// round 17
// speedup vs baseline: 1.0860x; 1.0860x over previous
#include <cuda_runtime.h>

#define BATCH 32
#define CIN   64
#define COUT  64
#define HW    64
#define PLANE 4096
#define KK    9
#define SSTR  144                 // words per channel row of S (max used idx 139)
#define SBUF  (CIN * SSTR)        // one buffer: 9216 words = 36864 B

#define FMA2(a, s, w) asm("fma.rn.f32x2 %0, %1, %2, %0;" : "+l"(a) : "l"(s), "l"(w))

// Scratch
__device__ float g_d[BATCH * COUT * PLANE];            // pre-norm conv output (~33.5 MB)
__device__ unsigned long long g_wt2[KK * CIN * COUT];  // weights pre-duplicated (w,w) [k][c][o]

__global__ void transpose_w(const float* __restrict__ w) {
    int idx = blockIdx.x * 256 + threadIdx.x;
    if (idx < COUT * CIN * KK) {
        int o = idx / (CIN * KK);
        int r = idx % (CIN * KK);
        int c = r / KK;
        int k = r % KK;
        const float v = w[idx];
        unsigned long long d;
        asm("mov.b64 %0, {%1, %1};" : "=l"(d) : "f"(v));
        g_wt2[(k * CIN + c) * COUT + o] = d;
    }
}

__global__ void dummy_kernel() {}

// Warp-specialized: 256 threads = 4 producer warps (gather+blend into S, double-buffered)
//                              + 4 consumer warps (8px x 8out register-tile GEMM).
// produce(k+1) overlaps gemm(k); one __syncthreads per k.
__global__ __launch_bounds__(256, 2)
void deform_kernel(const float* __restrict__ x,
                   const float* __restrict__ offset)
{
    extern __shared__ float S[];   // 2 * SBUF floats

    const int t   = threadIdx.x;
    const int seg = blockIdx.x & 31;
    const int b   = blockIdx.x >> 5;
    const bool is_prod = (t < 128);

    const float* xb   = x + (size_t)b * CIN * PLANE;
    const float* offb = offset + (size_t)b * (2 * KK) * PLANE;

    // ---- Producer state (t in [0,128)) : one pixel, all 64 channels ----
    const int pixP  = t & 127;
    const int gpixP = seg * 128 + pixP;
    const int rowP  = gpixP >> 6;
    const int colP  = gpixP & 63;
    const int sw    = pixP + ((pixP >> 5) << 2);   // swizzled pixel slot

    // ---- Consumer state (t in [128,256)) : og = 8-out group, pg = 8-px group ----
    const int t2 = t & 127;
    const int o0 = (t2 >> 4) << 3;   // 0,8,...,56
    const int pg = t2 & 15;
    const int sbOff = pg * 8 + ((pg >> 2) << 2);

    // acc[pixel-pair][o] : 8 px x 8 outs = 32 packed f32x2 (64 regs)
    unsigned long long acc[4][8];
    #pragma unroll
    for (int i = 0; i < 4; i++)
        #pragma unroll
        for (int j = 0; j < 8; j++) acc[i][j] = 0ull;

    // ---------------- producer routine (inlined per call site via lambda-ish macro) ----
    auto produce = [&](int k, float* buf) {
        const int ky = k / 3;
        const int kx = k - 3 * ky;
        const float oy = __ldg(offb + (2 * k)     * PLANE + gpixP);
        const float ox = __ldg(offb + (2 * k + 1) * PLANE + gpixP);
        const float py = (float)(rowP - 1 + ky) + oy;
        const float px = (float)(colP - 1 + kx) + ox;
        const float y0f = floorf(py), x0f = floorf(px);
        const float fy = py - y0f,  fx = px - x0f;
        const int y0 = (int)y0f, x0 = (int)x0f;
        const int y1 = y0 + 1,   x1 = x0 + 1;
        const float vy0 = (y0 >= 0 && y0 < HW) ? 1.f : 0.f;
        const float vy1 = (y1 >= 0 && y1 < HW) ? 1.f : 0.f;
        const float vx0 = (x0 >= 0 && x0 < HW) ? 1.f : 0.f;
        const float vx1 = (x1 >= 0 && x1 < HW) ? 1.f : 0.f;
        const int cy0 = min(max(y0, 0), HW - 1), cy1 = min(max(y1, 0), HW - 1);
        const int cx0 = min(max(x0, 0), HW - 1), cx1 = min(max(x1, 0), HW - 1);
        const float W00 = (1.f - fy) * (1.f - fx) * vy0 * vx0;
        const float W01 = (1.f - fy) * fx        * vy0 * vx1;
        const float W10 = fy        * (1.f - fx) * vy1 * vx0;
        const float W11 = fy        * fx         * vy1 * vx1;

        const float* p00 = xb + cy0 * HW + cx0;
        const float* p01 = xb + cy0 * HW + cx1;
        const float* p10 = xb + cy1 * HW + cx0;
        const float* p11 = xb + cy1 * HW + cx1;
        float* sd = buf + sw;

        #pragma unroll 8
        for (int cc = 0; cc < CIN; cc++) {
            const float a00 = __ldg(p00 + cc * PLANE);
            const float a01 = __ldg(p01 + cc * PLANE);
            const float a10 = __ldg(p10 + cc * PLANE);
            const float a11 = __ldg(p11 + cc * PLANE);
            float s = W00 * a00;
            s = fmaf(W01, a01, s);
            s = fmaf(W10, a10, s);
            s = fmaf(W11, a11, s);
            sd[cc * SSTR] = s;
        }
    };

    // Prologue: fill buffer 0 with tap 0
    if (is_prod) produce(0, S);
    __syncthreads();

    #pragma unroll 1
    for (int k = 0; k < KK; k++) {
        if (is_prod) {
            if (k < KK - 1) produce(k + 1, S + ((k + 1) & 1) * SBUF);
        } else {
            // ---------------- consumer: GEMM from S[k&1] x g_wt2 ----------------
            const float* sb = S + (k & 1) * SBUF + sbOff;
            const unsigned long long* wbase = g_wt2 + (size_t)k * CIN * COUT + o0;

            #pragma unroll 4
            for (int c = 0; c < CIN; c++) {
                const ulonglong2 wA = __ldg((const ulonglong2*)(wbase + (size_t)c * COUT));
                const ulonglong2 wB = __ldg((const ulonglong2*)(wbase + (size_t)c * COUT + 2));
                const ulonglong2 wC = __ldg((const ulonglong2*)(wbase + (size_t)c * COUT + 4));
                const ulonglong2 wD = __ldg((const ulonglong2*)(wbase + (size_t)c * COUT + 6));

                const ulonglong2 sA = *(const ulonglong2*)(sb + c * SSTR);
                const ulonglong2 sB = *(const ulonglong2*)(sb + c * SSTR + 4);

                FMA2(acc[0][0], sA.x, wA.x); FMA2(acc[1][0], sA.y, wA.x);
                FMA2(acc[2][0], sB.x, wA.x); FMA2(acc[3][0], sB.y, wA.x);
                FMA2(acc[0][1], sA.x, wA.y); FMA2(acc[1][1], sA.y, wA.y);
                FMA2(acc[2][1], sB.x, wA.y); FMA2(acc[3][1], sB.y, wA.y);
                FMA2(acc[0][2], sA.x, wB.x); FMA2(acc[1][2], sA.y, wB.x);
                FMA2(acc[2][2], sB.x, wB.x); FMA2(acc[3][2], sB.y, wB.x);
                FMA2(acc[0][3], sA.x, wB.y); FMA2(acc[1][3], sA.y, wB.y);
                FMA2(acc[2][3], sB.x, wB.y); FMA2(acc[3][3], sB.y, wB.y);
                FMA2(acc[0][4], sA.x, wC.x); FMA2(acc[1][4], sA.y, wC.x);
                FMA2(acc[2][4], sB.x, wC.x); FMA2(acc[3][4], sB.y, wC.x);
                FMA2(acc[0][5], sA.x, wC.y); FMA2(acc[1][5], sA.y, wC.y);
                FMA2(acc[2][5], sB.x, wC.y); FMA2(acc[3][5], sB.y, wC.y);
                FMA2(acc[0][6], sA.x, wD.x); FMA2(acc[1][6], sA.y, wD.x);
                FMA2(acc[2][6], sB.x, wD.x); FMA2(acc[3][6], sB.y, wD.x);
                FMA2(acc[0][7], sA.x, wD.y); FMA2(acc[1][7], sA.y, wD.y);
                FMA2(acc[2][7], sB.x, wD.y); FMA2(acc[3][7], sB.y, wD.y);
            }
        }
        __syncthreads();
    }

    // Epilogue: consumers write d (8 consecutive pixels per thread, per-o planes).
    if (!is_prod) {
        float* dbase = g_d + ((size_t)b * COUT + o0) * PLANE + seg * 128 + pg * 8;
        #pragma unroll
        for (int oo = 0; oo < 8; oo++) {
            float4 v0, v1;
            v0.x = __uint_as_float((unsigned)(acc[0][oo] & 0xffffffffull));
            v0.y = __uint_as_float((unsigned)(acc[0][oo] >> 32));
            v0.z = __uint_as_float((unsigned)(acc[1][oo] & 0xffffffffull));
            v0.w = __uint_as_float((unsigned)(acc[1][oo] >> 32));
            v1.x = __uint_as_float((unsigned)(acc[2][oo] & 0xffffffffull));
            v1.y = __uint_as_float((unsigned)(acc[2][oo] >> 32));
            v1.z = __uint_as_float((unsigned)(acc[3][oo] & 0xffffffffull));
            v1.w = __uint_as_float((unsigned)(acc[3][oo] >> 32));
            *(float4*)(dbase + (size_t)oo * PLANE)     = v0;
            *(float4*)(dbase + (size_t)oo * PLANE + 4) = v1;
        }
    }
}

// One block per (b, o) plane: single-read stats + normalize + tanh.
__global__ __launch_bounds__(256)
void norm_kernel(const float* __restrict__ gamma_p,
                 const float* __restrict__ beta_p,
                 float* __restrict__ out)
{
    __shared__ float red[16];
    __shared__ float bcast[2];

    const int bo = blockIdx.x;
    const int t  = threadIdx.x;
    const float4* src = reinterpret_cast<const float4*>(g_d + (size_t)bo * PLANE);

    float4 v[4];
    float s = 0.f, q = 0.f;
    #pragma unroll
    for (int i = 0; i < 4; i++) {
        v[i] = src[t + 256 * i];
        s += v[i].x + v[i].y + v[i].z + v[i].w;
        q += v[i].x * v[i].x + v[i].y * v[i].y + v[i].z * v[i].z + v[i].w * v[i].w;
    }
    #pragma unroll
    for (int d = 16; d > 0; d >>= 1) {
        s += __shfl_xor_sync(0xffffffffu, s, d);
        q += __shfl_xor_sync(0xffffffffu, q, d);
    }
    const int w = t >> 5, lane = t & 31;
    if (lane == 0) { red[w] = s; red[8 + w] = q; }
    __syncthreads();
    if (t == 0) {
        float S = 0.f, Q = 0.f;
        #pragma unroll
        for (int i = 0; i < 8; i++) { S += red[i]; Q += red[8 + i]; }
        const float n  = (float)PLANE;
        const float mu = S / n;
        float var = (Q - S * S / n) / (n - 1.f);
        var = fmaxf(var, 0.f);
        const float sd = sqrtf(var);
        bcast[0] = mu;
        bcast[1] = __ldg(gamma_p) / (sd + 1e-8f);
    }
    __syncthreads();
    const float mu    = bcast[0];
    const float scale = bcast[1];
    const float beta  = __ldg(beta_p);

    float4* o = reinterpret_cast<float4*>(out + (size_t)bo * PLANE);
    #pragma unroll
    for (int i = 0; i < 4; i++) {
        float4 r;
        r.x = tanhf((v[i].x - mu) * scale + beta);
        r.y = tanhf((v[i].y - mu) * scale + beta);
        r.z = tanhf((v[i].z - mu) * scale + beta);
        r.w = tanhf((v[i].w - mu) * scale + beta);
        o[t + 256 * i] = r;
    }
}

extern "C" void kernel_launch(void* const* d_in, const int* in_sizes, int n_in,
                              void* d_out, int out_size)
{
    const float* x      = (const float*)d_in[0];
    const float* offset = (const float*)d_in[1];
    const float* weight = (const float*)d_in[2];
    const float* gamma  = (const float*)d_in[3];
    const float* beta   = (const float*)d_in[4];

    cudaFuncSetAttribute(deform_kernel,
                         cudaFuncAttributeMaxDynamicSharedMemorySize,
                         2 * SBUF * (int)sizeof(float));

    // Launch order keeps deform at ncu position 3 (-s 5 with 2 harness pre-launches).
    transpose_w<<<144, 256>>>(weight);       // pos 0
    dummy_kernel<<<1, 32>>>();               // pos 1
    dummy_kernel<<<1, 32>>>();               // pos 2
    deform_kernel<<<BATCH * 32, 256, 2 * SBUF * sizeof(float)>>>(x, offset);  // pos 3
    norm_kernel<<<BATCH * COUT, 256>>>(gamma, beta, (float*)d_out);           // pos 4
}